// round 5
// baseline (speedup 1.0000x reference)
#include <cuda_runtime.h>

#define NB 64
#define NP 8732
#define NC 81
#define NO 16
#define NCHUNK 8
#define CHUNK 1092   // ceil(8732/8); 8*1092 = 8736 >= 8732

// ---------------- scratch (device globals; no allocation) ----------------
__device__ float              g_bto[NB * NP];        // best truth overlap per prior
__device__ unsigned char      g_bti[NB * NP];        // best truth idx per prior
__device__ unsigned long long g_bpkey[NB * NO];      // packed (iou_bits<<32)|(~p) argmax keys
__device__ int                g_conf[NB * NP];       // conf_t
__device__ float              g_ceneg[NB * NP];      // positive-zeroed CE
__device__ float              g_lossl[NB];
__device__ int                g_npos[NB];
__device__ float              g_cepos[NB];
__device__ float              g_topk[NB];

// ---------------- K0: zero the cross-kernel accumulators ----------------
__global__ void k_init() {
    int t = threadIdx.x;               // 1024 threads, 1 block
    if (t < NB * NO) g_bpkey[t] = 0ull;
    if (t < NB) { g_lossl[t] = 0.f; g_npos[t] = 0; g_cepos[t] = 0.f; }
}

// ---------------- K1: IoU matching (bit-exact vs reference) ----------------
// grid (NCHUNK, NB), 256 threads
__global__ __launch_bounds__(256) void k_iou(const float* __restrict__ dbox,
                                             const float* __restrict__ truths) {
    int b = blockIdx.y;
    int chunk = blockIdx.x;
    int tid = threadIdx.x;

    __shared__ float sh_t[NO][4];
    __shared__ float sh_area[NO];
    if (tid < NO) {
        float x0 = truths[(b * NO + tid) * 4 + 0];
        float y0 = truths[(b * NO + tid) * 4 + 1];
        float x1 = truths[(b * NO + tid) * 4 + 2];
        float y1 = truths[(b * NO + tid) * 4 + 3];
        sh_t[tid][0] = x0; sh_t[tid][1] = y0; sh_t[tid][2] = x1; sh_t[tid][3] = y1;
        sh_area[tid] = __fmul_rn(__fsub_rn(x1, x0), __fsub_rn(y1, y0));
    }
    __syncthreads();

    float bv[NO];
    int   bp_[NO];
#pragma unroll
    for (int o = 0; o < NO; o++) { bv[o] = -1.f; bp_[o] = 0; }

    int p0 = chunk * CHUNK;
    int p1 = p0 + CHUNK; if (p1 > NP) p1 = NP;

    for (int p = p0 + tid; p < p1; p += 256) {
        float4 db = reinterpret_cast<const float4*>(dbox)[p];
        // point_form: ctr -+ wh/2  (wh*0.5 exact; no contraction)
        float px0 = __fsub_rn(db.x, __fmul_rn(db.z, 0.5f));
        float py0 = __fsub_rn(db.y, __fmul_rn(db.w, 0.5f));
        float px1 = __fadd_rn(db.x, __fmul_rn(db.z, 0.5f));
        float py1 = __fadd_rn(db.y, __fmul_rn(db.w, 0.5f));
        float areab = __fmul_rn(__fsub_rn(px1, px0), __fsub_rn(py1, py0));

        float best = -1.f; int bi = 0;
#pragma unroll
        for (int o = 0; o < NO; o++) {
            float ix0 = fmaxf(px0, sh_t[o][0]);
            float iy0 = fmaxf(py0, sh_t[o][1]);
            float ix1 = fminf(px1, sh_t[o][2]);
            float iy1 = fminf(py1, sh_t[o][3]);
            float iw = fmaxf(__fsub_rn(ix1, ix0), 0.f);
            float ih = fmaxf(__fsub_rn(iy1, iy0), 0.f);
            float inter = __fmul_rn(iw, ih);
            float denom = __fsub_rn(__fadd_rn(sh_area[o], areab), inter);
            float iou = __fdiv_rn(inter, denom);
            if (iou > best) { best = iou; bi = o; }      // first-occurrence over o
            if (iou > bv[o]) { bv[o] = iou; bp_[o] = p; } // first-occurrence over p (ascending)
        }
        g_bto[b * NP + p] = best;
        g_bti[b * NP + p] = (unsigned char)bi;
    }

    // per-truth argmax over priors: pack (iou_bits << 32) | (~p); max key = max iou, min p
#pragma unroll
    for (int o = 0; o < NO; o++) {
        unsigned long long kk =
            (((unsigned long long)__float_as_uint(bv[o] < 0.f ? 0.f : bv[o])) << 32) |
            (unsigned long long)(0xFFFFFFFFu - (unsigned)bp_[o]);
#pragma unroll
        for (int s = 16; s > 0; s >>= 1) {
            unsigned long long other = __shfl_down_sync(0xFFFFFFFFu, kk, s);
            if (other > kk) kk = other;
        }
        if ((tid & 31) == 0) atomicMax(&g_bpkey[b * NO + o], kk);
    }
}

// ---------------- K2: assign conf_t, localization loss, num_pos ----------------
// grid (ceil(NP/256), NB), 256 threads
__global__ __launch_bounds__(256) void k_assign(const float* __restrict__ dbox,
                                                const float* __restrict__ truths,
                                                const int* __restrict__ labels,
                                                const float* __restrict__ loc_data) {
    int b = blockIdx.y;
    int p = blockIdx.x * 256 + threadIdx.x;
    int tid = threadIdx.x;

    __shared__ float sh_t[NO][4];
    __shared__ int sh_lab[NO];
    __shared__ int sh_bp[NO];
    if (tid < NO) {
        sh_t[tid][0] = truths[(b * NO + tid) * 4 + 0];
        sh_t[tid][1] = truths[(b * NO + tid) * 4 + 1];
        sh_t[tid][2] = truths[(b * NO + tid) * 4 + 2];
        sh_t[tid][3] = truths[(b * NO + tid) * 4 + 3];
        sh_lab[tid] = labels[b * NO + tid];
        sh_bp[tid] = (int)(0xFFFFFFFFu - (unsigned)(g_bpkey[b * NO + tid] & 0xFFFFFFFFull));
    }
    __syncthreads();

    float lsum = 0.f;
    int np = 0;
    if (p < NP) {
        int mo = -1;
#pragma unroll
        for (int o = 0; o < NO; o++)
            if (sh_bp[o] == p) mo = o;   // ascending o -> last write wins (scatter semantics)
        float ov; int ti;
        if (mo >= 0) { ov = 2.f; ti = mo; }
        else         { ov = g_bto[b * NP + p]; ti = (int)g_bti[b * NP + p]; }
        int c = (ov < 0.5f) ? 0 : (sh_lab[ti] + 1);
        g_conf[b * NP + p] = c;
        if (c > 0) {
            np = 1;
            float4 db = reinterpret_cast<const float4*>(dbox)[p];
            float x0 = sh_t[ti][0], y0 = sh_t[ti][1], x1 = sh_t[ti][2], y1 = sh_t[ti][3];
            float gx = ((x0 + x1) * 0.5f - db.x) / (0.1f * db.z);
            float gy = ((y0 + y1) * 0.5f - db.y) / (0.1f * db.w);
            float gw = logf((x1 - x0) / db.z) / 0.2f;
            float gh = logf((y1 - y0) / db.w) / 0.2f;
            float4 ld = reinterpret_cast<const float4*>(loc_data)[b * NP + p];
            float tgt[4] = {gx, gy, gw, gh};
            float lv[4] = {ld.x, ld.y, ld.z, ld.w};
#pragma unroll
            for (int j = 0; j < 4; j++) {
                float d = fabsf(lv[j] - tgt[j]);
                lsum += (d < 1.f) ? 0.5f * d * d : d - 0.5f;
            }
        }
    }
    // block reduce
#pragma unroll
    for (int s = 16; s > 0; s >>= 1) {
        lsum += __shfl_down_sync(0xFFFFFFFFu, lsum, s);
        np   += __shfl_down_sync(0xFFFFFFFFu, np, s);
    }
    __shared__ float rs[8];
    __shared__ int rn[8];
    int wid = tid >> 5, lane = tid & 31;
    if (lane == 0) { rs[wid] = lsum; rn[wid] = np; }
    __syncthreads();
    if (tid == 0) {
        float L = 0.f; int N = 0;
#pragma unroll
        for (int i = 0; i < 8; i++) { L += rs[i]; N += rn[i]; }
        if (L != 0.f) atomicAdd(&g_lossl[b], L);
        if (N != 0)   atomicAdd(&g_npos[b], N);
    }
}

// ---------------- K3: per-prior cross entropy (warp per prior) ----------------
__global__ __launch_bounds__(256) void k_ce(const float* __restrict__ conf) {
    int gw = (blockIdx.x * blockDim.x + threadIdx.x) >> 5;
    int lane = threadIdx.x & 31;
    if (gw >= NB * NP) return;
    const float* row = conf + (size_t)gw * NC;
    float v0 = row[lane];
    float v1 = row[lane + 32];
    float v2 = (lane < NC - 64) ? row[lane + 64] : -1e30f;
    float m = fmaxf(v0, fmaxf(v1, v2));
#pragma unroll
    for (int s = 16; s > 0; s >>= 1) m = fmaxf(m, __shfl_xor_sync(0xFFFFFFFFu, m, s));
    float e = __expf(v0 - m) + __expf(v1 - m) + ((lane < NC - 64) ? __expf(v2 - m) : 0.f);
#pragma unroll
    for (int s = 16; s > 0; s >>= 1) e += __shfl_xor_sync(0xFFFFFFFFu, e, s);
    if (lane == 0) {
        int c = g_conf[gw];
        float ce = m + __logf(e) - row[c];
        if (c > 0) {
            atomicAdd(&g_cepos[gw / NP], ce);
            g_ceneg[gw] = 0.f;
        } else {
            g_ceneg[gw] = ce;
        }
    }
}

// ---------------- K4: per-batch top-k sum via radix select ----------------
// grid (NB), 256 threads
__global__ __launch_bounds__(256) void k_topk() {
    int b = blockIdx.x, tid = threadIdx.x;
    const float* vals = g_ceneg + b * NP;
    int k = g_npos[b] * 3;
    if (k > NP) k = NP;
    if (k <= 0) { if (tid == 0) g_topk[b] = 0.f; return; }

    __shared__ int hist[256];
    __shared__ unsigned s_prefix;
    __shared__ int s_krem;
    if (tid == 0) { s_prefix = 0u; s_krem = k; }
    __syncthreads();

    for (int pass = 0; pass < 4; pass++) {
        int shift = 24 - pass * 8;
        hist[tid] = 0;
        __syncthreads();
        unsigned prefix = s_prefix;
        unsigned himask = (pass == 0) ? 0u : (0xFFFFFFFFu << (shift + 8));
        for (int p = tid; p < NP; p += 256) {
            unsigned u = __float_as_uint(vals[p]);
            if ((u & himask) == prefix)
                atomicAdd(&hist[(u >> shift) & 0xFF], 1);
        }
        __syncthreads();
        if (tid == 0) {
            int krem = s_krem, cum = 0, bin;
            for (bin = 255; bin > 0; bin--) {
                int h = hist[bin];
                if (cum + h >= krem) break;
                cum += h;
            }
            s_prefix = prefix | ((unsigned)bin << shift);
            s_krem = krem - cum;
        }
        __syncthreads();
    }
    unsigned t = s_prefix;  // exact bit pattern of the k-th largest value
    float sum = 0.f; int cnt = 0;
    for (int p = tid; p < NP; p += 256) {
        unsigned u = __float_as_uint(vals[p]);
        if (u > t) { sum += __uint_as_float(u); cnt++; }
    }
#pragma unroll
    for (int s = 16; s > 0; s >>= 1) {
        sum += __shfl_down_sync(0xFFFFFFFFu, sum, s);
        cnt += __shfl_down_sync(0xFFFFFFFFu, cnt, s);
    }
    __shared__ float rsum[8];
    __shared__ int rcnt[8];
    int wid = tid >> 5, lane = tid & 31;
    if (lane == 0) { rsum[wid] = sum; rcnt[wid] = cnt; }
    __syncthreads();
    if (tid == 0) {
        float S = 0.f; int Cn = 0;
#pragma unroll
        for (int i = 0; i < 8; i++) { S += rsum[i]; Cn += rcnt[i]; }
        g_topk[b] = S + (float)(k - Cn) * __uint_as_float(t);
    }
}

// ---------------- K5: finalize ----------------
__global__ void k_final(float* __restrict__ out) {
    int t = threadIdx.x;  // 64 threads
    float ll = g_lossl[t];
    int np = g_npos[t];
    float cc = g_cepos[t] + g_topk[t];
#pragma unroll
    for (int s = 16; s > 0; s >>= 1) {
        ll += __shfl_down_sync(0xFFFFFFFFu, ll, s);
        cc += __shfl_down_sync(0xFFFFFFFFu, cc, s);
        np += __shfl_down_sync(0xFFFFFFFFu, np, s);
    }
    __shared__ float sl[2], sc[2];
    __shared__ int sn[2];
    if ((t & 31) == 0) { sl[t >> 5] = ll; sc[t >> 5] = cc; sn[t >> 5] = np; }
    __syncthreads();
    if (t == 0) {
        float L = sl[0] + sl[1];
        float Cx = sc[0] + sc[1];
        float Nf = (float)(sn[0] + sn[1]);
        out[0] = L / Nf;
        out[1] = Cx / Nf;
    }
}

// ---------------- launch ----------------
extern "C" void kernel_launch(void* const* d_in, const int* in_sizes, int n_in,
                              void* d_out, int out_size) {
    const float* loc_data  = (const float*)d_in[0];
    const float* conf_data = (const float*)d_in[1];
    const float* dbox      = (const float*)d_in[2];
    const float* truths    = (const float*)d_in[3];
    const int*   labels    = (const int*)d_in[4];
    float* out = (float*)d_out;

    k_init<<<1, 1024>>>();

    dim3 g1(NCHUNK, NB);
    k_iou<<<g1, 256>>>(dbox, truths);

    dim3 g2((NP + 255) / 256, NB);
    k_assign<<<g2, 256>>>(dbox, truths, labels, loc_data);

    int nwarps = NB * NP;                 // one warp per (b, p)
    k_ce<<<(nwarps * 32 + 255) / 256, 256>>>(conf_data);

    k_topk<<<NB, 256>>>();

    k_final<<<1, 64>>>(out);
}